// round 5
// baseline (speedup 1.0000x reference)
#include <cuda_runtime.h>
#include <cstdint>

#define BATCH 512
#define CHANNELS 256
#define KXS 6
#define KZ 22
#define HO 17
#define OUT_PER_B 289
#define N_OUT (BATCH*OUT_PER_B)

#define SPLITS 4
#define CH_PER_SPLIT 64
#define CH_CHUNK 32                 // channels per staged chunk (16 pairs)
#define PAIRS 16
#define ITERS (CH_PER_SPLIT/CH_CHUNK)   // 2
#define THREADS 272                 // 17 rows x 16 pair lanes

#define ZPAIR_FLOATS (KZ*KZ*2)      // 968 floats per channel-pair
#define ZROW_PAIRF 44               // 22 pairs * 2 floats per row
#define XPAIR_FLOATS (KXS*KXS*2)    // 72
#define Z_SMEM_FLOATS (PAIRS*ZPAIR_FLOATS)   // 15488
#define X_SMEM_FLOATS (PAIRS*XPAIR_FLOATS)   // 1152
#define SMEM_BYTES ((Z_SMEM_FLOATS + X_SMEM_FLOATS) * 4)   // 66560

#define Z_UNITS (PAIRS*121)         // 1936 float4-pairs per chunk
#define X_UNITS (PAIRS*9)           // 144

typedef unsigned long long ull;

__device__ float g_partial[SPLITS * N_OUT];

__device__ __forceinline__ void fma2(ull& d, ull a, ull b) {
    asm("fma.rn.f32x2 %0, %1, %2, %0;" : "+l"(d) : "l"(a), "l"(b));
}
__device__ __forceinline__ void unpack2(ull v, float& lo, float& hi) {
    asm("mov.b64 {%0, %1}, %2;" : "=f"(lo), "=f"(hi) : "l"(v));
}

__global__ __launch_bounds__(THREADS, 2)
void corr_main_kernel(const float* __restrict__ x, const float* __restrict__ z)
{
    extern __shared__ float smem[];
    float* zbuf = smem;                       // 15488 floats
    float* xbuf = smem + Z_SMEM_FLOATS;       // 1152 floats

    const int tid = threadIdx.x;
    const int i   = tid % HO;     // output row owned by this thread
    const int pl  = tid / HO;     // pair lane 0..15

    const int b     = blockIdx.x >> 2;
    const int split = blockIdx.x & 3;
    const int cbase = split * CH_PER_SPLIT;

    ull acc[HO];
    #pragma unroll
    for (int j = 0; j < HO; j++) acc[j] = 0ull;

    for (int it = 0; it < ITERS; ++it) {
        const int c0 = cbase + it * CH_CHUNK;
        if (it) __syncthreads();   // previous chunk fully consumed

        // ---- stage z: interleave channel pairs ----
        {
            const float4* zg = reinterpret_cast<const float4*>(
                z + ((size_t)b * CHANNELS + c0) * (KZ * KZ));
            for (int u = tid; u < Z_UNITS; u += THREADS) {
                int p  = u / 121;          // pair index
                int w4 = u - p * 121;      // float4 index within channel (0..120)
                const float4* src = zg + (size_t)(2 * p) * 121 + w4;
                float4 a = src[0];         // channel 2p
                float4 c = src[121];       // channel 2p+1
                float4 lo = make_float4(a.x, c.x, a.y, c.y);
                float4 hi = make_float4(a.z, c.z, a.w, c.w);
                float4* dst = reinterpret_cast<float4*>(
                    zbuf + p * ZPAIR_FLOATS + 8 * w4);
                dst[0] = lo;
                dst[1] = hi;
            }
        }
        // ---- stage x pairs ----
        if (tid < X_UNITS) {
            int p  = tid / 9;
            int w4 = tid - p * 9;
            const float4* src = reinterpret_cast<const float4*>(
                x + ((size_t)b * CHANNELS + c0) * (KXS * KXS))
                + (size_t)(2 * p) * 9 + w4;
            float4 a = src[0];
            float4 c = src[9];
            float4 lo = make_float4(a.x, c.x, a.y, c.y);
            float4 hi = make_float4(a.z, c.z, a.w, c.w);
            float4* dst = reinterpret_cast<float4*>(
                xbuf + p * XPAIR_FLOATS + 8 * w4);
            dst[0] = lo;
            dst[1] = hi;
        }
        __syncthreads();

        // ---- compute: channel pair pl, output row i ----
        const float* zc = zbuf + pl * ZPAIR_FLOATS;
        const float* xc = xbuf + pl * XPAIR_FLOATS;
        #pragma unroll
        for (int ky = 0; ky < KXS; ky++) {
            ull zp[22];
            const ulonglong2* zr = reinterpret_cast<const ulonglong2*>(
                zc + (i + ky) * ZROW_PAIRF);
            #pragma unroll
            for (int q = 0; q < 11; q++) {
                ulonglong2 t = zr[q];
                zp[2*q]   = t.x;
                zp[2*q+1] = t.y;
            }
            const ull* xr = reinterpret_cast<const ull*>(xc + ky * (KXS * 2));
            #pragma unroll
            for (int kx = 0; kx < KXS; kx++) {
                ull xx = xr[kx];
                #pragma unroll
                for (int j = 0; j < HO; j++)
                    fma2(acc[j], zp[j + kx], xx);
            }
        }
    }

    // ---- fold pair lanes, then reduce 16 pair-lanes via smem ----
    __syncthreads();   // done reading zbuf; reuse as scratch (16*289 floats)
    #pragma unroll
    for (int j = 0; j < HO; j++) {
        float lo, hi;
        unpack2(acc[j], lo, hi);
        zbuf[pl * OUT_PER_B + i * HO + j] = lo + hi;
    }
    __syncthreads();

    for (int o = tid; o < OUT_PER_B; o += THREADS) {
        float s = 0.f;
        #pragma unroll
        for (int p = 0; p < PAIRS; p++)
            s += zbuf[p * OUT_PER_B + o];
        g_partial[((size_t)split * BATCH + b) * OUT_PER_B + o] = s;
    }
}

__global__ void corr_reduce_kernel(float* __restrict__ out)
{
    int idx = blockIdx.x * blockDim.x + threadIdx.x;
    if (idx < N_OUT) {
        out[idx] = g_partial[idx]
                 + g_partial[N_OUT + idx]
                 + g_partial[2 * N_OUT + idx]
                 + g_partial[3 * N_OUT + idx];
    }
}

extern "C" void kernel_launch(void* const* d_in, const int* in_sizes, int n_in,
                              void* d_out, int out_size)
{
    const float* a = (const float*)d_in[0];
    const float* bptr = (const float*)d_in[1];
    const float* x;
    const float* z;
    if (in_sizes[0] == BATCH * CHANNELS * KXS * KXS) { x = a;    z = bptr; }
    else                                             { x = bptr; z = a;   }

    float* out = (float*)d_out;

    cudaFuncSetAttribute(corr_main_kernel,
                         cudaFuncAttributeMaxDynamicSharedMemorySize, SMEM_BYTES);

    corr_main_kernel<<<BATCH * SPLITS, THREADS, SMEM_BYTES>>>(x, z);
    corr_reduce_kernel<<<(N_OUT + 255) / 256, 256>>>(out);
}

// round 6
// speedup vs baseline: 1.0029x; 1.0029x over previous
#include <cuda_runtime.h>
#include <cstdint>

#define BATCH 512
#define CHANNELS 256
#define KXS 6
#define KZ 22
#define HO 17
#define OUT_PER_B 289
#define N_OUT (BATCH*OUT_PER_B)

#define SPLITS 4
#define CH_PER_SPLIT 64
#define CH_CHUNK 32                 // channels per staged chunk (16 pairs)
#define PAIRS 16
#define ITERS (CH_PER_SPLIT/CH_CHUNK)   // 2
#define THREADS 272                 // 17 rows x 16 pair lanes

#define ZPAIR_FLOATS (KZ*KZ*2)      // 968 floats per channel-pair
#define ZROW_PAIRF 44               // 22 pairs * 2 floats per row
#define XPAIR_FLOATS (KXS*KXS*2)    // 72
#define Z_SMEM_FLOATS (PAIRS*ZPAIR_FLOATS)   // 15488
#define X_SMEM_FLOATS (PAIRS*XPAIR_FLOATS)   // 1152
#define SMEM_BYTES ((Z_SMEM_FLOATS + X_SMEM_FLOATS) * 4)   // 66560

#define Z_UNITS (PAIRS*121)         // 1936 float4-pairs per chunk
#define X_UNITS (PAIRS*9)           // 144

typedef unsigned long long ull;

__device__ float g_partial[SPLITS * N_OUT];

__device__ __forceinline__ void fma2(ull& d, ull a, ull b) {
    asm("fma.rn.f32x2 %0, %1, %2, %0;" : "+l"(d) : "l"(a), "l"(b));
}
__device__ __forceinline__ void unpack2(ull v, float& lo, float& hi) {
    asm("mov.b64 {%0, %1}, %2;" : "=f"(lo), "=f"(hi) : "l"(v));
}

__global__ __launch_bounds__(THREADS, 2)
void corr_main_kernel(const float* __restrict__ x, const float* __restrict__ z)
{
    extern __shared__ float smem[];
    float* zbuf = smem;                       // 15488 floats
    float* xbuf = smem + Z_SMEM_FLOATS;       // 1152 floats

    const int tid = threadIdx.x;
    const int i   = tid % HO;     // output row owned by this thread
    const int pl  = tid / HO;     // pair lane 0..15

    const int b     = blockIdx.x >> 2;
    const int split = blockIdx.x & 3;
    const int cbase = split * CH_PER_SPLIT;

    ull acc[HO];
    #pragma unroll
    for (int j = 0; j < HO; j++) acc[j] = 0ull;

    for (int it = 0; it < ITERS; ++it) {
        const int c0 = cbase + it * CH_CHUNK;
        if (it) __syncthreads();   // previous chunk fully consumed

        // ---- stage z: interleave channel pairs ----
        {
            const float4* zg = reinterpret_cast<const float4*>(
                z + ((size_t)b * CHANNELS + c0) * (KZ * KZ));
            for (int u = tid; u < Z_UNITS; u += THREADS) {
                int p  = u / 121;          // pair index
                int w4 = u - p * 121;      // float4 index within channel
                const float4* src = zg + (size_t)(2 * p) * 121 + w4;
                float4 a = src[0];         // channel 2p
                float4 c = src[121];       // channel 2p+1
                float4 lo = make_float4(a.x, c.x, a.y, c.y);
                float4 hi = make_float4(a.z, c.z, a.w, c.w);
                float4* dst = reinterpret_cast<float4*>(
                    zbuf + p * ZPAIR_FLOATS + 8 * w4);
                dst[0] = lo;
                dst[1] = hi;
            }
        }
        // ---- stage x pairs ----
        if (tid < X_UNITS) {
            int p  = tid / 9;
            int w4 = tid - p * 9;
            const float4* src = reinterpret_cast<const float4*>(
                x + ((size_t)b * CHANNELS + c0) * (KXS * KXS))
                + (size_t)(2 * p) * 9 + w4;
            float4 a = src[0];
            float4 c = src[9];
            float4 lo = make_float4(a.x, c.x, a.y, c.y);
            float4 hi = make_float4(a.z, c.z, a.w, c.w);
            float4* dst = reinterpret_cast<float4*>(
                xbuf + p * XPAIR_FLOATS + 8 * w4);
            dst[0] = lo;
            dst[1] = hi;
        }
        __syncthreads();

        // ---- compute: channel pair pl, output row i ----
        const float* zc = zbuf + pl * ZPAIR_FLOATS;
        const float* xc = xbuf + pl * XPAIR_FLOATS;
        #pragma unroll
        for (int ky = 0; ky < KXS; ky++) {
            const ull* zrow = reinterpret_cast<const ull*>(
                zc + (i + ky) * ZROW_PAIRF);        // 22 pair entries
            // x taps for this ky (3x LDS.128, broadcast within pair-lane)
            ull xx[6];
            {
                const ulonglong2* x2 = reinterpret_cast<const ulonglong2*>(
                    xc + ky * (KXS * 2));
                ulonglong2 t0 = x2[0], t1 = x2[1], t2 = x2[2];
                xx[0] = t0.x; xx[1] = t0.y;
                xx[2] = t1.x; xx[3] = t1.y;
                xx[4] = t2.x; xx[5] = t2.y;
            }

            // ---- half A: positions 0..12 (13 ull live) ----
            {
                ull zp[13];
                const ulonglong2* z2 = reinterpret_cast<const ulonglong2*>(zrow);
                #pragma unroll
                for (int q = 0; q < 6; q++) {
                    ulonglong2 t = z2[q];
                    zp[2*q]   = t.x;
                    zp[2*q+1] = t.y;
                }
                zp[12] = zrow[12];
                #pragma unroll
                for (int kx = 0; kx < KXS; kx++) {
                    #pragma unroll
                    for (int j = 0; j <= 12 - kx; j++)
                        fma2(acc[j], zp[j + kx], xx[kx]);
                }
            }
            // ---- half B: positions 13..21 (9 ull live) ----
            {
                ull zq[9];
                zq[0] = zrow[13];
                const ulonglong2* z2 = reinterpret_cast<const ulonglong2*>(zrow + 14);
                #pragma unroll
                for (int q = 0; q < 4; q++) {
                    ulonglong2 t = z2[q];
                    zq[1 + 2*q] = t.x;
                    zq[2 + 2*q] = t.y;
                }
                #pragma unroll
                for (int kx = 0; kx < KXS; kx++) {
                    #pragma unroll
                    for (int j = 13 - kx; j < HO; j++)
                        fma2(acc[j], zq[j + kx - 13], xx[kx]);
                }
            }
        }
    }

    // ---- fold pair lanes, then reduce 16 pair-lanes via smem ----
    __syncthreads();   // done reading zbuf; reuse as scratch
    #pragma unroll
    for (int j = 0; j < HO; j++) {
        float lo, hi;
        unpack2(acc[j], lo, hi);
        zbuf[pl * OUT_PER_B + i * HO + j] = lo + hi;
    }
    __syncthreads();

    for (int o = tid; o < OUT_PER_B; o += THREADS) {
        float s = 0.f;
        #pragma unroll
        for (int p = 0; p < PAIRS; p++)
            s += zbuf[p * OUT_PER_B + o];
        g_partial[((size_t)split * BATCH + b) * OUT_PER_B + o] = s;
    }
}

__global__ void corr_reduce_kernel(float* __restrict__ out)
{
    int idx = blockIdx.x * blockDim.x + threadIdx.x;
    if (idx < N_OUT) {
        out[idx] = g_partial[idx]
                 + g_partial[N_OUT + idx]
                 + g_partial[2 * N_OUT + idx]
                 + g_partial[3 * N_OUT + idx];
    }
}

extern "C" void kernel_launch(void* const* d_in, const int* in_sizes, int n_in,
                              void* d_out, int out_size)
{
    const float* a = (const float*)d_in[0];
    const float* bptr = (const float*)d_in[1];
    const float* x;
    const float* z;
    if (in_sizes[0] == BATCH * CHANNELS * KXS * KXS) { x = a;    z = bptr; }
    else                                             { x = bptr; z = a;   }

    float* out = (float*)d_out;

    cudaFuncSetAttribute(corr_main_kernel,
                         cudaFuncAttributeMaxDynamicSharedMemorySize, SMEM_BYTES);

    corr_main_kernel<<<BATCH * SPLITS, THREADS, SMEM_BYTES>>>(x, z);
    corr_reduce_kernel<<<(N_OUT + 255) / 256, 256>>>(out);
}